// round 2
// baseline (speedup 1.0000x reference)
#include <cuda_runtime.h>
#include <cstdint>
#include <cstddef>

// ---------------- problem constants ----------------
#define N_ATOMS 50000
#define M_NBR   12
#define R_TOT   600000          // N_ATOMS * M_NBR
#define NTILES  4688            // ceil(R_TOT/128)
#define R_PAD   600064          // NTILES*128
#define ORIG_F  200
#define AFL     64
#define CO      128             // 2*AFL
#define K2      192
#define N0      5000

#define MSG_GRID  296
#define GATE_GRID 1250          // 40 atoms / block

#define XCS 36                  // X chunk smem stride (floats)
#define WCS 136                 // W chunk smem stride (floats)

// ---------------- device scratch (no allocations allowed) ----------------
__device__ float g_atom[(size_t)N_ATOMS * AFL];
__device__ float g_Z[(size_t)R_PAD * CO];          // ~307 MB
__device__ float g_summed[(size_t)N_ATOMS * AFL];
__device__ float g_part2[MSG_GRID * 256];          // per-block [sum(128) | sumsq(128)]
__device__ float g_part1[GATE_GRID * 128];         // per-block [sum(64)  | sumsq(64)]
__device__ float g_sc2[CO], g_sh2[CO];
__device__ float g_sc1[AFL], g_sh1[AFL];
__device__ int   g_idx64;

// ---------------- helpers ----------------
__device__ __forceinline__ float tf32r(float x) {
    unsigned u;
    asm("cvt.rna.tf32.f32 %0, %1;" : "=r"(u) : "f"(x));
    return __uint_as_float(u);
}

__device__ __forceinline__ void mma_tf32(float* d, const unsigned* a, const unsigned* b) {
    asm volatile(
        "mma.sync.aligned.m16n8k8.row.col.f32.tf32.tf32.f32 "
        "{%0,%1,%2,%3},{%4,%5,%6,%7},{%8,%9},{%0,%1,%2,%3};"
        : "+f"(d[0]), "+f"(d[1]), "+f"(d[2]), "+f"(d[3])
        : "r"(a[0]), "r"(a[1]), "r"(a[2]), "r"(a[3]), "r"(b[0]), "r"(b[1]));
}

__device__ __forceinline__ float softplusf(float x) {
    return fmaxf(x, 0.f) + log1pf(__expf(-fabsf(x)));
}

// ---------------- idx dtype sniffer ----------------
__global__ void k_detect(const unsigned* __restrict__ p) {
    if (threadIdx.x == 0) {
        int all0 = 1;
#pragma unroll
        for (int i = 0; i < 32; i++) all0 &= (p[2 * i + 1] == 0u);
        g_idx64 = all0;
    }
}

// ---------------- embedding: atom = orig @ emb_W + emb_b ----------------
__global__ __launch_bounds__(256) void k_emb(const float* __restrict__ orig,
                                             const float* __restrict__ W,
                                             const float* __restrict__ b) {
    __shared__ float so[16 * ORIG_F];
    int n0 = blockIdx.x * 16;
    int t = threadIdx.x;
    for (int i = t; i < 16 * ORIG_F; i += 256)
        so[i] = orig[(size_t)n0 * ORIG_F + i];
    __syncthreads();
    int j = t & 63, g = t >> 6;
    float acc[4] = {0.f, 0.f, 0.f, 0.f};
    for (int k = 0; k < ORIG_F; k++) {
        float w = W[k * AFL + j];
#pragma unroll
        for (int q = 0; q < 4; q++) acc[q] += so[(g + q * 4) * ORIG_F + k] * w;
    }
    float bb = b[j];
#pragma unroll
    for (int q = 0; q < 4; q++)
        g_atom[(size_t)(n0 + g + q * 4) * AFL + j] = acc[q] + bb;
}

// ---------------- message GEMM (tf32 MMA) + bn2 stats partials ----------------
__global__ __launch_bounds__(256, 2) void k_msg(const float* __restrict__ nbr_fea,
                                                const void* __restrict__ idxp,
                                                const float* __restrict__ Wg) {
    __shared__ float Xc[128 * XCS];   // 18432 B
    __shared__ float Wc[32 * WCS];    // 17408 B

    const int t = threadIdx.x, lane = t & 31, wid = t >> 5;
    const int wm = wid >> 1, wn = wid & 1;
    const int g = lane >> 2, tg = lane & 3;
    const int row = t >> 1, half = t & 1;
    const int is64 = g_idx64;

    float ssum[16], ssq[16];
#pragma unroll
    for (int i = 0; i < 16; i++) { ssum[i] = 0.f; ssq[i] = 0.f; }

    for (int tile = blockIdx.x; tile < NTILES; tile += MSG_GRID) {
        float acc[2][8][4];
#pragma unroll
        for (int mt = 0; mt < 2; mt++)
#pragma unroll
            for (int nt = 0; nt < 8; nt++)
#pragma unroll
                for (int c = 0; c < 4; c++) acc[mt][nt][c] = 0.f;

        const int base = tile * 128;
        const int gr = base + row;

        for (int ch = 0; ch < 6; ch++) {
            __syncthreads();
            // stage W chunk (rows ch*32..+32, all 128 cols), tf32-rounded
            for (int i = t; i < 32 * 128; i += 256) {
                int kk = i >> 7, n = i & 127;
                Wc[kk * WCS + n] = tf32r(Wg[(ch * 32 + kk) * CO + n]);
            }
            // stage X chunk: 2 threads/row, 16 floats each
            float* xr = Xc + row * XCS + half * 16;
            if (gr < R_TOT) {
                const float* src;
                if (ch < 2) {
                    int n = gr / 12;
                    src = g_atom + (size_t)n * AFL + ch * 32;
                } else if (ch < 4) {
                    long long gi = is64 ? ((const long long*)idxp)[gr]
                                        : (long long)((const int*)idxp)[gr];
                    src = g_atom + (size_t)gi * AFL + (ch - 2) * 32;
                } else {
                    src = nbr_fea + (size_t)gr * AFL + (ch - 4) * 32;
                }
                const float4* s4 = (const float4*)src + half * 4;
#pragma unroll
                for (int q = 0; q < 4; q++) {
                    float4 v = s4[q];
                    xr[q * 4 + 0] = tf32r(v.x);
                    xr[q * 4 + 1] = tf32r(v.y);
                    xr[q * 4 + 2] = tf32r(v.z);
                    xr[q * 4 + 3] = tf32r(v.w);
                }
            } else {
#pragma unroll
                for (int q = 0; q < 16; q++) xr[q] = 0.f;
            }
            __syncthreads();

            // 4 k-steps of m16n8k8
#pragma unroll
            for (int ks = 0; ks < 4; ks++) {
                unsigned a[2][4];
                const float* xb = Xc + (wm * 32 + g) * XCS + ks * 8 + tg;
#pragma unroll
                for (int mt = 0; mt < 2; mt++) {
                    const float* xp = xb + mt * 16 * XCS;
                    a[mt][0] = __float_as_uint(xp[0]);
                    a[mt][1] = __float_as_uint(xp[8 * XCS]);
                    a[mt][2] = __float_as_uint(xp[4]);
                    a[mt][3] = __float_as_uint(xp[8 * XCS + 4]);
                }
                const float* wb = Wc + (ks * 8 + tg) * WCS + wn * 64 + g;
#pragma unroll
                for (int nt = 0; nt < 8; nt++) {
                    unsigned b[2];
                    b[0] = __float_as_uint(wb[nt * 8]);
                    b[1] = __float_as_uint(wb[4 * WCS + nt * 8]);
#pragma unroll
                    for (int mt = 0; mt < 2; mt++) mma_tf32(acc[mt][nt], a[mt], b);
                }
            }
        }

        // store Z + accumulate per-thread column stats
#pragma unroll
        for (int mt = 0; mt < 2; mt++) {
            int r0 = base + wm * 32 + mt * 16 + g;
#pragma unroll
            for (int nt = 0; nt < 8; nt++) {
                int c0 = wn * 64 + nt * 8 + 2 * tg;
                float v0 = acc[mt][nt][0], v1 = acc[mt][nt][1];
                float v2 = acc[mt][nt][2], v3 = acc[mt][nt][3];
                *(float2*)&g_Z[(size_t)r0 * CO + c0] = make_float2(v0, v1);
                *(float2*)&g_Z[(size_t)(r0 + 8) * CO + c0] = make_float2(v2, v3);
                ssum[nt * 2 + 0] += v0 + v2;
                ssum[nt * 2 + 1] += v1 + v3;
                ssq[nt * 2 + 0] += v0 * v0 + v2 * v2;
                ssq[nt * 2 + 1] += v1 * v1 + v3 * v3;
            }
        }
    }

    // deterministic fixed-order block reduction of stats (reuse Xc)
    __syncthreads();
    float* buf = Xc;   // need 256*16 = 4096 floats (Xc holds 4608)
    for (int pass = 0; pass < 2; pass++) {
        const float* src = pass ? ssq : ssum;
#pragma unroll
        for (int i = 0; i < 16; i++) buf[t * 16 + i] = src[i];
        __syncthreads();
        if (t < 128) {
            int wn_ = t >> 6, jj = t & 63, nt = jj >> 3, r = jj & 7;
            int tg_ = r >> 1, b = r & 1;
            float s = 0.f;
            for (int q = 0; q < 32; q++) {
                int wm_ = q >> 3, g_ = q & 7;
                int tt = (wm_ * 2 + wn_) * 32 + g_ * 4 + tg_;
                s += buf[tt * 16 + nt * 2 + b];
            }
            g_part2[blockIdx.x * 256 + pass * 128 + t] = s;
        }
        __syncthreads();
    }
}

// ---------------- bn2 finalize ----------------
__global__ void k_bn2fin(const float* __restrict__ gamma, const float* __restrict__ beta) {
    int j = threadIdx.x;   // 128 threads
    float s = 0.f, q = 0.f;
    for (int b = 0; b < MSG_GRID; b++) {
        s += g_part2[b * 256 + j];
        q += g_part2[b * 256 + 128 + j];
    }
    float mean = s / (float)R_TOT;
    float var = q / (float)R_TOT - mean * mean;
    float sc = gamma[j] * rsqrtf(var + 1e-5f);
    g_sc2[j] = sc;
    g_sh2[j] = beta[j] - mean * sc;
}

// ---------------- gate: summed = sum_m sigmoid(bn f)*softplus(bn c) ----------------
__global__ __launch_bounds__(256) void k_gate() {
    int t = threadIdx.x, j = t & 63, al = t >> 6;
    float sc_f = g_sc2[j], sh_f = g_sh2[j];
    float sc_c = g_sc2[64 + j], sh_c = g_sh2[64 + j];
    float ls = 0.f, lq = 0.f;
    int a0 = blockIdx.x * 40;
    for (int it = 0; it < 10; it++) {
        int n = a0 + it * 4 + al;
        float accv = 0.f;
        const float* zr = g_Z + (size_t)n * 12 * CO;
#pragma unroll
        for (int m = 0; m < 12; m++) {
            float f = zr[m * CO + j] * sc_f + sh_f;
            float c = zr[m * CO + 64 + j] * sc_c + sh_c;
            float sig = 1.f / (1.f + __expf(-f));
            accv += sig * softplusf(c);
        }
        g_summed[(size_t)n * AFL + j] = accv;
        ls += accv;
        lq += accv * accv;
    }
    __shared__ float rb[512];
    rb[t] = ls; rb[256 + t] = lq;
    __syncthreads();
    if (t < 64) {
        float s = rb[t] + rb[t + 64] + rb[t + 128] + rb[t + 192];
        float q = rb[256 + t] + rb[256 + t + 64] + rb[256 + t + 128] + rb[256 + t + 192];
        g_part1[blockIdx.x * 128 + t] = s;
        g_part1[blockIdx.x * 128 + 64 + t] = q;
    }
}

// ---------------- bn1 finalize ----------------
__global__ void k_bn1fin(const float* __restrict__ gamma, const float* __restrict__ beta) {
    int j = threadIdx.x;   // 64 threads
    float s = 0.f, q = 0.f;
    for (int b = 0; b < GATE_GRID; b++) {
        s += g_part1[b * 128 + j];
        q += g_part1[b * 128 + 64 + j];
    }
    float mean = s / (float)N_ATOMS;
    float var = q / (float)N_ATOMS - mean * mean;
    float sc = gamma[j] * rsqrtf(var + 1e-5f);
    g_sc1[j] = sc;
    g_sh1[j] = beta[j] - mean * sc;
}

// ---------------- residual update: atom = softplus(atom + bn1(summed)) ----------------
__global__ __launch_bounds__(256) void k_update() {
    size_t i = (size_t)blockIdx.x * 256 + threadIdx.x;
    int j = (int)(i & 63);
    float v = g_atom[i] + g_sc1[j] * g_summed[i] + g_sh1[j];
    g_atom[i] = softplusf(v);
}

// ---------------- pooling + head MLP ----------------
__global__ __launch_bounds__(128) void k_pool(const float* __restrict__ fc1W,
                                              const float* __restrict__ fc1b,
                                              const float* __restrict__ outW,
                                              const float* __restrict__ outb,
                                              float* __restrict__ out) {
    int c = blockIdx.x, t = threadIdx.x;
    __shared__ float sp[128];
    if (t < 64) {
        const float* ap = g_atom + (size_t)c * 10 * AFL + t;
        float s = 0.f;
#pragma unroll
        for (int m = 0; m < 10; m++) s += ap[m * AFL];
        float mean = s * 0.1f;
        float q = 0.f;
#pragma unroll
        for (int m = 0; m < 10; m++) { float d = ap[m * AFL] - mean; q += d * d; }
        float stdv = sqrtf(q * (1.f / 9.f));
        sp[t] = softplusf(mean);
        sp[64 + t] = softplusf(stdv);
    }
    __syncthreads();
    float h = fc1b[t];
    for (int k = 0; k < 128; k++) h += sp[k] * fc1W[k * 128 + t];
    h = softplusf(h);
    __shared__ float rr[128];
    rr[t] = h * outW[t];
    __syncthreads();
    for (int s = 64; s > 0; s >>= 1) {
        if (t < s) rr[t] += rr[t + s];
        __syncthreads();
    }
    if (t == 0) out[c] = rr[0] + outb[0];
}

// ---------------- launch ----------------
extern "C" void kernel_launch(void* const* d_in, const int* in_sizes, int n_in,
                              void* d_out, int out_size) {
    const float* orig    = (const float*)d_in[0];
    const float* nbr_fea = (const float*)d_in[1];
    const void*  idx     = d_in[2];
    // d_in[3] segment_ids: provably i/10, unused
    const float* embW = (const float*)d_in[4];
    const float* embb = (const float*)d_in[5];
    const float* msgW = (const float*)d_in[6];
    // d_in[7] msg_b: dead under training-mode BN
    const float* bn2g = (const float*)d_in[8];
    const float* bn2b = (const float*)d_in[9];
    const float* bn1g = (const float*)d_in[10];
    const float* bn1b = (const float*)d_in[11];
    const float* fc1W = (const float*)d_in[12];
    const float* fc1b = (const float*)d_in[13];
    const float* outW = (const float*)d_in[14];
    const float* outb = (const float*)d_in[15];
    float* out = (float*)d_out;

    k_detect<<<1, 32>>>((const unsigned*)idx);
    k_emb<<<N_ATOMS / 16, 256>>>(orig, embW, embb);

    for (int i = 0; i < 3; i++) {
        k_msg<<<MSG_GRID, 256>>>(nbr_fea, idx, msgW + (size_t)i * K2 * CO);
        k_bn2fin<<<1, 128>>>(bn2g + i * CO, bn2b + i * CO);
        k_gate<<<GATE_GRID, 256>>>();
        k_bn1fin<<<1, 64>>>(bn1g + i * AFL, bn1b + i * AFL);
        k_update<<<(N_ATOMS * AFL) / 256, 256>>>();
    }

    k_pool<<<N0, 128>>>(fc1W, fc1b, outW, outb, out);
}

// round 5
// speedup vs baseline: 1.3261x; 1.3261x over previous
#include <cuda_runtime.h>
#include <cuda_fp16.h>
#include <cstdint>
#include <cstddef>

// ---------------- problem constants ----------------
#define N_ATOMS 50000
#define M_NBR   12
#define R_TOT   600000
#define NTILES  4688            // ceil(R_TOT/128)
#define R_PAD   600064
#define ORIG_F  200
#define AFL     64
#define CO      128
#define K2      192
#define N0      5000

#define MSG_GRID  296
#define GATE_GRID 500           // 100 atoms / block

#define XCS 36                  // X smem row stride (32 used + 4 pad), 144B = 16B-aligned
#define WCS 136                 // W smem row stride
#define NCH 6                   // 192 / 32

// ---------------- device scratch ----------------
__device__ float  g_atom[(size_t)N_ATOMS * AFL];
__device__ __half g_Zh[(size_t)R_PAD * CO];        // ~154 MB
__device__ float  g_summed[(size_t)N_ATOMS * AFL];
__device__ float  g_part2[MSG_GRID * 256];
__device__ float  g_part1[GATE_GRID * 128];
__device__ float  g_sc2[CO], g_sh2[CO];
__device__ float  g_sc1[AFL], g_sh1[AFL];
__device__ int    g_idx64;

// ---------------- helpers ----------------
__device__ __forceinline__ void mma_tf32(float* d, const unsigned* a, const unsigned* b) {
    asm volatile(
        "mma.sync.aligned.m16n8k8.row.col.f32.tf32.tf32.f32 "
        "{%0,%1,%2,%3},{%4,%5,%6,%7},{%8,%9},{%0,%1,%2,%3};"
        : "+f"(d[0]), "+f"(d[1]), "+f"(d[2]), "+f"(d[3])
        : "r"(a[0]), "r"(a[1]), "r"(a[2]), "r"(a[3]), "r"(b[0]), "r"(b[1]));
}

__device__ __forceinline__ float softplusf(float x) {
    return fmaxf(x, 0.f) + __logf(1.f + __expf(-fabsf(x)));
}

// ---------------- idx dtype sniffer (idempotent) ----------------
__global__ void k_detect(const unsigned* __restrict__ p) {
    if (threadIdx.x == 0) {
        int all0 = 1;
#pragma unroll
        for (int i = 0; i < 32; i++) all0 &= (p[2 * i + 1] == 0u);
        g_idx64 = all0;
    }
}

// ---------------- embedding ----------------
__global__ __launch_bounds__(256) void k_emb(const float* __restrict__ orig,
                                             const float* __restrict__ W,
                                             const float* __restrict__ b) {
    __shared__ float so[16 * ORIG_F];
    int n0 = blockIdx.x * 16;
    int t = threadIdx.x;
    for (int i = t; i < 16 * ORIG_F; i += 256)
        so[i] = orig[(size_t)n0 * ORIG_F + i];
    __syncthreads();
    int j = t & 63, g = t >> 6;
    float acc[4] = {0.f, 0.f, 0.f, 0.f};
    for (int k = 0; k < ORIG_F; k++) {
        float w = W[k * AFL + j];
#pragma unroll
        for (int q = 0; q < 4; q++) acc[q] += so[(g + q * 4) * ORIG_F + k] * w;
    }
    float bb = b[j];
#pragma unroll
    for (int q = 0; q < 4; q++)
        g_atom[(size_t)(n0 + g + q * 4) * AFL + j] = acc[q] + bb;
}

// ---------------- message GEMM: register-prefetch pipelined tf32 MMA ----------------
// Per 128-row tile: K=192 in 6 chunks of 32. While MMAing chunk ch from smem,
// chunk ch+1's global loads are already in flight into registers.
__global__ __launch_bounds__(256, 2) void k_msg(const float* __restrict__ nbr_fea,
                                                const void* __restrict__ idxp,
                                                const float* __restrict__ Wg) {
    __shared__ float Xc[128 * XCS];   // 18432 B
    __shared__ float Wc[32 * WCS];    // 17408 B
    __shared__ int   sIdx[128];

    const int t = threadIdx.x, lane = t & 31, wid = t >> 5;
    const int wm = wid >> 1, wn = wid & 1;
    const int g = lane >> 2, tg = lane & 3;
    const int is64 = g_idx64;

    // X staging: 2 threads/row, 16 floats each
    const int row = t >> 1, half = t & 1;
    // W staging: 8 threads/row (32 rows x 128 cols), 16 floats each
    const int wrow = t >> 3, wcb = (t & 7) * 16;

    float ssum[16], ssq[16];
#pragma unroll
    for (int i = 0; i < 16; i++) { ssum[i] = 0.f; ssq[i] = 0.f; }

    for (int tile = blockIdx.x; tile < NTILES; tile += MSG_GRID) {
        const int base = tile * 128;
        const int gr = base + row;
        const bool vld = gr < R_TOT;
        const int nSelf = gr / M_NBR;

        __syncthreads();   // previous tile fully done
        if (t < 128) {
            int g2 = base + t;
            int gi = 0;
            if (g2 < R_TOT)
                gi = is64 ? (int)((const long long*)idxp)[g2] : ((const int*)idxp)[g2];
            sIdx[t] = gi;
        }
        __syncthreads();   // sIdx visible

        float4 xr[4], wr[4];
        const float zero4w = 0.f; (void)zero4w;

        auto loadX = [&](int ch) {
            if (vld) {
                const float* src;
                if (ch < 2)      src = g_atom + (size_t)nSelf * AFL + ch * 32;
                else if (ch < 4) src = g_atom + (size_t)sIdx[row] * AFL + (ch - 2) * 32;
                else             src = nbr_fea + (size_t)gr * AFL + (ch - 4) * 32;
                const float4* s4 = (const float4*)src + half * 4;
                xr[0] = s4[0]; xr[1] = s4[1]; xr[2] = s4[2]; xr[3] = s4[3];
            } else {
                float4 z = make_float4(0.f, 0.f, 0.f, 0.f);
                xr[0] = z; xr[1] = z; xr[2] = z; xr[3] = z;
            }
        };
        auto loadW = [&](int ch) {
            const float4* s4 = (const float4*)(Wg + (size_t)(ch * 32 + wrow) * CO + wcb);
            wr[0] = s4[0]; wr[1] = s4[1]; wr[2] = s4[2]; wr[3] = s4[3];
        };
        auto storeXW = [&]() {
            float4* xd = (float4*)(Xc + row * XCS + half * 16);
            xd[0] = xr[0]; xd[1] = xr[1]; xd[2] = xr[2]; xd[3] = xr[3];
            float4* wd = (float4*)(Wc + wrow * WCS + wcb);
            wd[0] = wr[0]; wd[1] = wr[1]; wd[2] = wr[2]; wd[3] = wr[3];
        };

        float acc[2][8][4];
#pragma unroll
        for (int mt = 0; mt < 2; mt++)
#pragma unroll
            for (int nt = 0; nt < 8; nt++)
#pragma unroll
                for (int c = 0; c < 4; c++) acc[mt][nt][c] = 0.f;

        // prologue: chunk 0 to smem
        loadX(0); loadW(0);
        storeXW();

        for (int ch = 0; ch < NCH; ch++) {
            __syncthreads();   // chunk ch visible in smem
            // issue next chunk's global loads (overlap with MMAs below)
            if (ch + 1 < NCH) { loadX(ch + 1); loadW(ch + 1); }

#pragma unroll
            for (int ks = 0; ks < 4; ks++) {
                unsigned a[2][4];
#pragma unroll
                for (int mt = 0; mt < 2; mt++) {
                    const float* xp = Xc + (wm * 32 + mt * 16 + g) * XCS + ks * 8 + tg;
                    a[mt][0] = __float_as_uint(xp[0]);
                    a[mt][1] = __float_as_uint(xp[8 * XCS]);
                    a[mt][2] = __float_as_uint(xp[4]);
                    a[mt][3] = __float_as_uint(xp[8 * XCS + 4]);
                }
                const float* wb = Wc + (ks * 8 + tg) * WCS + wn * 64 + g;
#pragma unroll
                for (int nt = 0; nt < 8; nt++) {
                    unsigned b[2];
                    b[0] = __float_as_uint(wb[nt * 8]);
                    b[1] = __float_as_uint(wb[4 * WCS + nt * 8]);
#pragma unroll
                    for (int mt = 0; mt < 2; mt++) mma_tf32(acc[mt][nt], a[mt], b);
                }
            }

            __syncthreads();   // all warps done reading smem chunk ch
            if (ch + 1 < NCH) storeXW();
        }

        // epilogue: fp16 Z store + column stats
#pragma unroll
        for (int mt = 0; mt < 2; mt++) {
            int r0 = base + wm * 32 + mt * 16 + g;
#pragma unroll
            for (int nt = 0; nt < 8; nt++) {
                int c0 = wn * 64 + nt * 8 + 2 * tg;
                float v0 = acc[mt][nt][0], v1 = acc[mt][nt][1];
                float v2 = acc[mt][nt][2], v3 = acc[mt][nt][3];
                *(__half2*)&g_Zh[(size_t)r0 * CO + c0] = __floats2half2_rn(v0, v1);
                *(__half2*)&g_Zh[(size_t)(r0 + 8) * CO + c0] = __floats2half2_rn(v2, v3);
                ssum[nt * 2 + 0] += v0 + v2;
                ssum[nt * 2 + 1] += v1 + v3;
                ssq[nt * 2 + 0] += v0 * v0 + v2 * v2;
                ssq[nt * 2 + 1] += v1 * v1 + v3 * v3;
            }
        }
    }

    // deterministic fixed-order block reduction of stats (reuse Xc: need 4096 floats)
    __syncthreads();
    float* buf = Xc;
    for (int pass = 0; pass < 2; pass++) {
        const float* src = pass ? ssq : ssum;
#pragma unroll
        for (int i = 0; i < 16; i++) buf[t * 16 + i] = src[i];
        __syncthreads();
        if (t < 128) {
            int wn_ = t >> 6, jj = t & 63, nt = jj >> 3, r = jj & 7;
            int tg_ = r >> 1, b = r & 1;
            float s = 0.f;
            for (int q = 0; q < 32; q++) {
                int wm_ = q >> 3, g_ = q & 7;
                int tt = (wm_ * 2 + wn_) * 32 + g_ * 4 + tg_;
                s += buf[tt * 16 + nt * 2 + b];
            }
            g_part2[blockIdx.x * 256 + pass * 128 + t] = s;
        }
        __syncthreads();
    }
}

// ---------------- bn2 finalize (parallel) ----------------
__global__ __launch_bounds__(1024) void k_bn2fin(const float* __restrict__ gamma,
                                                 const float* __restrict__ beta) {
    __shared__ float red[2048];
    int t = threadIdx.x, j = t & 127, sl = t >> 7;   // 8 slices x 128 cols
    float s = 0.f, q = 0.f;
    for (int b = sl; b < MSG_GRID; b += 8) {
        s += g_part2[b * 256 + j];
        q += g_part2[b * 256 + 128 + j];
    }
    red[t] = s; red[1024 + t] = q;
    __syncthreads();
    if (t < 128) {
        float S = 0.f, Q = 0.f;
#pragma unroll
        for (int k = 0; k < 8; k++) { S += red[k * 128 + t]; Q += red[1024 + k * 128 + t]; }
        float mean = S / (float)R_TOT;
        float var = Q / (float)R_TOT - mean * mean;
        float sc = gamma[t] * rsqrtf(var + 1e-5f);
        g_sc2[t] = sc;
        g_sh2[t] = beta[t] - mean * sc;
    }
}

// ---------------- gate ----------------
__global__ __launch_bounds__(256) void k_gate() {
    int t = threadIdx.x, j = t & 63, al = t >> 6;
    float sc_f = g_sc2[j], sh_f = g_sh2[j];
    float sc_c = g_sc2[64 + j], sh_c = g_sh2[64 + j];
    float ls = 0.f, lq = 0.f;
    int a0 = blockIdx.x * 100;
    for (int it = 0; it < 25; it++) {
        int n = a0 + it * 4 + al;
        const __half* zr = g_Zh + (size_t)n * M_NBR * CO;
        float accv = 0.f;
#pragma unroll
        for (int m = 0; m < 12; m++) {
            float f = __half2float(zr[m * CO + j]) * sc_f + sh_f;
            float c = __half2float(zr[m * CO + 64 + j]) * sc_c + sh_c;
            float sig = __fdividef(1.f, 1.f + __expf(-f));
            accv += sig * softplusf(c);
        }
        g_summed[(size_t)n * AFL + j] = accv;
        ls += accv;
        lq += accv * accv;
    }
    __shared__ float rb[512];
    rb[t] = ls; rb[256 + t] = lq;
    __syncthreads();
    if (t < 64) {
        float s = rb[t] + rb[t + 64] + rb[t + 128] + rb[t + 192];
        float q = rb[256 + t] + rb[256 + t + 64] + rb[256 + t + 128] + rb[256 + t + 192];
        g_part1[blockIdx.x * 128 + t] = s;
        g_part1[blockIdx.x * 128 + 64 + t] = q;
    }
}

// ---------------- bn1 finalize (parallel) ----------------
__global__ __launch_bounds__(1024) void k_bn1fin(const float* __restrict__ gamma,
                                                 const float* __restrict__ beta) {
    __shared__ float red[2048];
    int t = threadIdx.x, j = t & 63, sl = t >> 6;   // 16 slices x 64 cols
    float s = 0.f, q = 0.f;
    for (int b = sl; b < GATE_GRID; b += 16) {
        s += g_part1[b * 128 + j];
        q += g_part1[b * 128 + 64 + j];
    }
    red[t] = s; red[1024 + t] = q;
    __syncthreads();
    if (t < 64) {
        float S = 0.f, Q = 0.f;
#pragma unroll
        for (int k = 0; k < 16; k++) { S += red[k * 64 + t]; Q += red[1024 + k * 64 + t]; }
        float mean = S / (float)N_ATOMS;
        float var = Q / (float)N_ATOMS - mean * mean;
        float sc = gamma[t] * rsqrtf(var + 1e-5f);
        g_sc1[t] = sc;
        g_sh1[t] = beta[t] - mean * sc;
    }
}

// ---------------- residual update ----------------
__global__ __launch_bounds__(256) void k_update() {
    size_t i = (size_t)blockIdx.x * 256 + threadIdx.x;
    int j = (int)(i & 63);
    float v = g_atom[i] + g_sc1[j] * g_summed[i] + g_sh1[j];
    g_atom[i] = softplusf(v);
}

// ---------------- pooling + head ----------------
__global__ __launch_bounds__(128) void k_pool(const float* __restrict__ fc1W,
                                              const float* __restrict__ fc1b,
                                              const float* __restrict__ outW,
                                              const float* __restrict__ outb,
                                              float* __restrict__ out) {
    int c = blockIdx.x, t = threadIdx.x;
    __shared__ float sp[128];
    if (t < 64) {
        const float* ap = g_atom + (size_t)c * 10 * AFL + t;
        float s = 0.f;
#pragma unroll
        for (int m = 0; m < 10; m++) s += ap[m * AFL];
        float mean = s * 0.1f;
        float q = 0.f;
#pragma unroll
        for (int m = 0; m < 10; m++) { float d = ap[m * AFL] - mean; q += d * d; }
        float stdv = sqrtf(q * (1.f / 9.f));
        sp[t] = softplusf(mean);
        sp[64 + t] = softplusf(stdv);
    }
    __syncthreads();
    float h = fc1b[t];
    for (int k = 0; k < 128; k++) h += sp[k] * fc1W[k * 128 + t];
    h = softplusf(h);
    __shared__ float rr[128];
    rr[t] = h * outW[t];
    __syncthreads();
    for (int s = 64; s > 0; s >>= 1) {
        if (t < s) rr[t] += rr[t + s];
        __syncthreads();
    }
    if (t == 0) out[c] = rr[0] + outb[0];
}

// ---------------- launch ----------------
extern "C" void kernel_launch(void* const* d_in, const int* in_sizes, int n_in,
                              void* d_out, int out_size) {
    const float* orig    = (const float*)d_in[0];
    const float* nbr_fea = (const float*)d_in[1];
    const void*  idx     = d_in[2];
    const float* embW = (const float*)d_in[4];
    const float* embb = (const float*)d_in[5];
    const float* msgW = (const float*)d_in[6];
    const float* bn2g = (const float*)d_in[8];
    const float* bn2b = (const float*)d_in[9];
    const float* bn1g = (const float*)d_in[10];
    const float* bn1b = (const float*)d_in[11];
    const float* fc1W = (const float*)d_in[12];
    const float* fc1b = (const float*)d_in[13];
    const float* outW = (const float*)d_in[14];
    const float* outb = (const float*)d_in[15];
    float* out = (float*)d_out;

    // 4x idempotent detect: aligns ncu -s 5 -c 1 onto the first k_msg
    for (int r = 0; r < 4; r++) k_detect<<<1, 32>>>((const unsigned*)idx);
    k_emb<<<N_ATOMS / 16, 256>>>(orig, embW, embb);

    for (int i = 0; i < 3; i++) {
        k_msg<<<MSG_GRID, 256>>>(nbr_fea, idx, msgW + (size_t)i * K2 * CO);
        k_bn2fin<<<1, 1024>>>(bn2g + i * CO, bn2b + i * CO);
        k_gate<<<GATE_GRID, 256>>>();
        k_bn1fin<<<1, 1024>>>(bn1g + i * AFL, bn1b + i * AFL);
        k_update<<<(N_ATOMS * AFL) / 256, 256>>>();
    }

    k_pool<<<N0, 128>>>(fc1W, fc1b, outW, outb, out);
}